// round 7
// baseline (speedup 1.0000x reference)
#include <cuda_runtime.h>
#include <math.h>

#define EPS 1e-5f

// Problem dims (fixed by setup_inputs)
#define B_    2
#define C_    256
#define NPIX  4096   // 64*64
#define HEADS 8
#define HD    32
#define AREA  4
#define NA    1024   // NPIX/AREA

#define PSP 132      // Ps pitch (floats), 16B-aligned rows
#define VSP 36       // Vsm pitch (floats), even+16B-aligned for ulonglong2 loads

typedef unsigned long long u64;

// ---- packed f32x2 helpers (sm_103a FFMA2 path; ptxas won't auto-fuse) ----
__device__ __forceinline__ u64 pk2(float lo, float hi) {
    u64 r; asm("mov.b64 %0, {%1, %2};" : "=l"(r) : "f"(lo), "f"(hi)); return r;
}
__device__ __forceinline__ float2 up2(u64 v) {
    float2 f; asm("mov.b64 {%0, %1}, %2;" : "=f"(f.x), "=f"(f.y) : "l"(v)); return f;
}
__device__ __forceinline__ u64 ffma2(u64 a, u64 b, u64 c) {
    u64 d; asm("fma.rn.f32x2 %0, %1, %2, %3;" : "=l"(d) : "l"(a), "l"(b), "l"(c)); return d;
}
__device__ __forceinline__ u64 fmul2(u64 a, u64 b) {
    u64 d; asm("mul.rn.f32x2 %0, %1, %2;" : "=l"(d) : "l"(a), "l"(b)); return d;
}

// ---------------- scratch (device globals, no allocation) ----------------
__device__ float g_qk[(size_t)B_ * 512 * NPIX];   // qk conv+BN output (B,512,N)
__device__ float g_v [(size_t)B_ * C_  * NPIX];   // v conv+BN output  (B,256,N)
__device__ float g_pp[(size_t)B_ * C_  * NPIX];   // PE conv+BN output (B,256,N)
__device__ float g_o [(size_t)B_ * C_  * NPIX];   // attention output  (B,256,N)

// =====================================================================
// Kernel 1: fused qk (512 oc) + v (256 oc) 1x1 conv GEMM with folded BN.
// Tiles 64oc x 128pix, 256 thr, micro 4x8 via f32x2 pairs.
// A stored DUPLICATED in smem so broadcast operand is a natural b64 load.
// =====================================================================
__global__ void __launch_bounds__(256, 2) k_qkv(
    const float* __restrict__ x,
    const float* __restrict__ w_qk, const float* __restrict__ w_v,
    const float* __restrict__ qk_g, const float* __restrict__ qk_b,
    const float* __restrict__ qk_m, const float* __restrict__ qk_v,
    const float* __restrict__ v_g,  const float* __restrict__ v_b,
    const float* __restrict__ v_m,  const float* __restrict__ v_v)
{
    __shared__ float As2[16 * 128];  // [c16][oc64 duplicated]   8KB
    __shared__ float Bs [16 * 128];  // [c16][pix128]            8KB

    const int tid = threadIdx.x;
    const int p0  = blockIdx.x * 128;
    const int b   = p0 >> 12;
    const int n0  = p0 & (NPIX - 1);
    const int oc0 = blockIdx.y * 64;
    const int ty  = tid >> 4, tx = tid & 15;

    u64 acc[4][4];
#pragma unroll
    for (int i = 0; i < 4; i++)
#pragma unroll
        for (int j = 0; j < 4; j++) acc[i][j] = 0ULL;

    // W loader: 4 threads per oc row, 4 consecutive c each
    const int row_l = tid >> 2;
    const int cpart = (tid & 3) * 4;
    const int ocg   = oc0 + row_l;
    const float* wrow = (ocg < 512) ? (w_qk + (size_t)ocg * 256)
                                    : (w_v  + (size_t)(ocg - 512) * 256);
    u64* As2u = (u64*)As2;

    for (int c0 = 0; c0 < 256; c0 += 16) {
        float4 w = *(const float4*)(wrow + c0 + cpart);
        As2u[(cpart + 0) * 64 + row_l] = pk2(w.x, w.x);
        As2u[(cpart + 1) * 64 + row_l] = pk2(w.y, w.y);
        As2u[(cpart + 2) * 64 + row_l] = pk2(w.z, w.z);
        As2u[(cpart + 3) * 64 + row_l] = pk2(w.w, w.w);
#pragma unroll
        for (int it = 0; it < 2; it++) {
            int e4 = tid + it * 256;          // 0..511 float4s
            int c_l = e4 >> 5, p4 = e4 & 31;
            float4 xv = *(const float4*)(x + (((size_t)(b * 256 + c0 + c_l)) << 12)
                                           + n0 + p4 * 4);
            *(float4*)(Bs + c_l * 128 + p4 * 4) = xv;
        }
        __syncthreads();
#pragma unroll
        for (int kk = 0; kk < 16; kk++) {
            const u64* Au = (const u64*)As2 + kk * 64 + ty * 4;
            ulonglong2 a01 = *(const ulonglong2*)(Au);
            ulonglong2 a23 = *(const ulonglong2*)(Au + 2);
            const u64* Bu = (const u64*)Bs + kk * 64 + tx * 4;
            ulonglong2 b01 = *(const ulonglong2*)(Bu);
            ulonglong2 b23 = *(const ulonglong2*)(Bu + 2);
            u64 av[4] = {a01.x, a01.y, a23.x, a23.y};
            u64 bv[4] = {b01.x, b01.y, b23.x, b23.y};
#pragma unroll
            for (int i = 0; i < 4; i++)
#pragma unroll
                for (int j = 0; j < 4; j++) acc[i][j] = ffma2(av[i], bv[j], acc[i][j]);
        }
        __syncthreads();
    }

#pragma unroll
    for (int i = 0; i < 4; i++) {
        int oc = oc0 + ty * 4 + i;
        float s, t;
        float* dst;
        if (oc < 512) {
            float sc = __ldg(qk_g + oc) * rsqrtf(__ldg(qk_v + oc) + EPS);
            s = sc; t = __ldg(qk_b + oc) - __ldg(qk_m + oc) * sc;
            dst = g_qk + (((size_t)(b * 512 + oc)) << 12) + n0;
        } else {
            int o2 = oc - 512;
            float sc = __ldg(v_g + o2) * rsqrtf(__ldg(v_v + o2) + EPS);
            s = sc; t = __ldg(v_b + o2) - __ldg(v_m + o2) * sc;
            dst = g_v + (((size_t)(b * 256 + o2)) << 12) + n0;
        }
        float2 f0 = up2(acc[i][0]), f1 = up2(acc[i][1]);
        float2 f2 = up2(acc[i][2]), f3 = up2(acc[i][3]);
        *(float4*)(dst + tx * 8)     = make_float4(f0.x * s + t, f0.y * s + t,
                                                   f1.x * s + t, f1.y * s + t);
        *(float4*)(dst + tx * 8 + 4) = make_float4(f2.x * s + t, f2.y * s + t,
                                                   f3.x * s + t, f3.y * s + t);
    }
}

// =====================================================================
// Kernel 2: depthwise 5x5 PE conv (cross-correlation, pad 2) + BN on g_v
// =====================================================================
__global__ void __launch_bounds__(256) k_pe(
    const float* __restrict__ w_pe,
    const float* __restrict__ pe_g, const float* __restrict__ pe_b,
    const float* __restrict__ pe_m, const float* __restrict__ pe_v)
{
    int id = blockIdx.x * 256 + threadIdx.x;     // < 2*256*4096
    int n  = id & 4095;
    int bc = id >> 12;
    int c  = bc & 255;
    int hh = n >> 6, w = n & 63;
    const float* vptr = g_v + ((size_t)bc << 12);
    const float* wp   = w_pe + c * 25;
    float acc = 0.f;
#pragma unroll
    for (int ky = 0; ky < 5; ky++) {
        int y = hh + ky - 2;
        if ((unsigned)y < 64u) {
#pragma unroll
            for (int kx = 0; kx < 5; kx++) {
                int xx = w + kx - 2;
                if ((unsigned)xx < 64u)
                    acc += vptr[y * 64 + xx] * __ldg(wp + ky * 5 + kx);
            }
        }
    }
    float sc = __ldg(pe_g + c) * rsqrtf(__ldg(pe_v + c) + EPS);
    g_pp[id] = acc * sc + (__ldg(pe_b + c) - __ldg(pe_m + c) * sc);
}

// =====================================================================
// Kernel 3: attention. Block = (n-tile of 128 rows) x (ba,head).
// Online softmax over 8 K/V chunks of 128. Na=1024, hd=32.
// S-phase and PV-phase on f32x2 pairs. Q stored duplicated.
// smem: Qs2[32][256](dup), Ks[32][128], Vsm[128][VSP], Ps[128][PSP],
//       sc_s[128], rs_s[128]
// =====================================================================
#define ATT_SMEM_FLOATS (32*256 + 32*128 + 128*VSP + 128*PSP + 128 + 128)
#define ATT_SMEM_BYTES  (ATT_SMEM_FLOATS * 4)

__global__ void __launch_bounds__(256, 1) k_attn()
{
    extern __shared__ float sm[];
    float* Qs2  = sm;                    // [d][2*n]  dup pairs, pitch 256
    float* Ks   = Qs2 + 32 * 256;        // [d][m]    pitch 128
    float* Vsm  = Ks + 32 * 128;         // [m][d]    pitch VSP (transposed)
    float* Ps   = Vsm + 128 * VSP;       // [n][m]    pitch PSP (reused as Os[d][n])
    float* sc_s = Ps + 128 * PSP;
    float* rs_s = sc_s + 128;

    const int tid   = threadIdx.x;
    const int tileN = blockIdx.x;        // 0..7
    const int bah   = blockIdx.y;        // 0..63
    const int ba = bah >> 3, h = bah & 7;
    const int b  = ba >> 2,  a = ba & 3;
    const int n0 = tileN * 128;
    const float qscale = 0.17677669529663687f;   // 32^-0.5

    const size_t qbase = (((size_t)(b * 512 + h * 32)) << 12) + a * 1024 + n0;
    const size_t kbase = (((size_t)(b * 512 + 256 + h * 32)) << 12) + a * 1024;
    const size_t vbase = (((size_t)(b * 256 + h * 32)) << 12) + a * 1024;

    // load Q tile (scaled, duplicated pairs)
#pragma unroll
    for (int it = 0; it < 4; it++) {
        int e4 = tid + it * 256;              // 0..1023 float4s
        int d = e4 >> 5, c4 = e4 & 31;
        float4 qv = *(const float4*)(g_qk + qbase + (size_t)d * 4096 + c4 * 4);
        qv.x *= qscale; qv.y *= qscale; qv.z *= qscale; qv.w *= qscale;
        u64* Qu = (u64*)Qs2 + d * 128 + c4 * 4;
        ulonglong2 q01; q01.x = pk2(qv.x, qv.x); q01.y = pk2(qv.y, qv.y);
        ulonglong2 q23; q23.x = pk2(qv.z, qv.z); q23.y = pk2(qv.w, qv.w);
        *(ulonglong2*)(Qu)     = q01;
        *(ulonglong2*)(Qu + 2) = q23;
    }

    const int ty  = tid >> 4, tx  = tid & 15;   // softmax ownership (8n x 8m micro)
    // PV ownership: warp-consecutive rows for conflict-free P reads
    const int wrp = tid >> 5;
    const int tyl = (tid >> 3) & 3;
    const int txo = tid & 7;
    int rrow[4];
#pragma unroll
    for (int i = 0; i < 4; i++) rrow[i] = wrp * 16 + tyl + 4 * i;

    float rm[8], rs[8];
#pragma unroll
    for (int i = 0; i < 8; i++) { rm[i] = -1e30f; rs[i] = 0.f; }
    u64 o2[4][2];
#pragma unroll
    for (int i = 0; i < 4; i++) { o2[i][0] = 0ULL; o2[i][1] = 0ULL; }

    __syncthreads();

    for (int m0 = 0; m0 < NA; m0 += 128) {
        // ---- load K chunk (float4) and V chunk (transposed, scalar) ----
#pragma unroll
        for (int it = 0; it < 4; it++) {
            int e4 = tid + it * 256;
            int d = e4 >> 5, c4 = e4 & 31;
            float4 kv = *(const float4*)(g_qk + kbase + (size_t)d * 4096 + m0 + c4 * 4);
            *(float4*)(Ks + d * 128 + c4 * 4) = kv;
        }
#pragma unroll
        for (int it = 0; it < 16; it++) {
            int e = tid + it * 256;               // 0..4095
            int d = e >> 7, m = e & 127;
            Vsm[m * VSP + d] = g_v[vbase + (size_t)d * 4096 + m0 + m];
        }
        __syncthreads();

        // ---- S = (Q^T K) chunk: 8 rows x 4 col-pairs of f32x2 ----
        u64 s2[8][4];
#pragma unroll
        for (int i = 0; i < 8; i++)
#pragma unroll
            for (int j = 0; j < 4; j++) s2[i][j] = 0ULL;
#pragma unroll
        for (int d = 0; d < 32; d++) {
            const u64* Qu = (const u64*)Qs2 + d * 128 + ty * 8;
            ulonglong2 qa = *(const ulonglong2*)(Qu);
            ulonglong2 qb = *(const ulonglong2*)(Qu + 2);
            ulonglong2 qc = *(const ulonglong2*)(Qu + 4);
            ulonglong2 qd = *(const ulonglong2*)(Qu + 6);
            const u64* Ku = (const u64*)Ks + d * 64 + tx * 4;
            ulonglong2 k01 = *(const ulonglong2*)(Ku);
            ulonglong2 k23 = *(const ulonglong2*)(Ku + 2);
            u64 qv[8] = {qa.x, qa.y, qb.x, qb.y, qc.x, qc.y, qd.x, qd.y};
            u64 kv[4] = {k01.x, k01.y, k23.x, k23.y};
#pragma unroll
            for (int i = 0; i < 8; i++)
#pragma unroll
                for (int j = 0; j < 4; j++) s2[i][j] = ffma2(qv[i], kv[j], s2[i][j]);
        }

        // ---- online softmax per row (half-warp of 16 shares a row set) ----
#pragma unroll
        for (int i = 0; i < 8; i++) {
            float2 u0 = up2(s2[i][0]), u1 = up2(s2[i][1]);
            float2 u2 = up2(s2[i][2]), u3 = up2(s2[i][3]);
            float sv[8] = {u0.x, u0.y, u1.x, u1.y, u2.x, u2.y, u3.x, u3.y};
            float cm = sv[0];
#pragma unroll
            for (int j = 1; j < 8; j++) cm = fmaxf(cm, sv[j]);
            cm = fmaxf(cm, __shfl_xor_sync(0xffffffffu, cm, 1, 16));
            cm = fmaxf(cm, __shfl_xor_sync(0xffffffffu, cm, 2, 16));
            cm = fmaxf(cm, __shfl_xor_sync(0xffffffffu, cm, 4, 16));
            cm = fmaxf(cm, __shfl_xor_sync(0xffffffffu, cm, 8, 16));
            float newm = fmaxf(rm[i], cm);
            float sc   = __expf(rm[i] - newm);
            float p[8], psum = 0.f;
#pragma unroll
            for (int j = 0; j < 8; j++) { p[j] = __expf(sv[j] - newm); psum += p[j]; }
            psum += __shfl_xor_sync(0xffffffffu, psum, 1, 16);
            psum += __shfl_xor_sync(0xffffffffu, psum, 2, 16);
            psum += __shfl_xor_sync(0xffffffffu, psum, 4, 16);
            psum += __shfl_xor_sync(0xffffffffu, psum, 8, 16);
            rs[i] = rs[i] * sc + psum;
            rm[i] = newm;
            int n = ty * 8 + i;
            if (tx == 0) sc_s[n] = sc;
            *(float4*)(Ps + n * PSP + tx * 8)     = make_float4(p[0], p[1], p[2], p[3]);
            *(float4*)(Ps + n * PSP + tx * 8 + 4) = make_float4(p[4], p[5], p[6], p[7]);
        }
        __syncthreads();

        // ---- O = O*sc + P @ V^T : 4 rows x 2 d-pairs of f32x2 ----
#pragma unroll
        for (int i = 0; i < 4; i++) {
            float sc = sc_s[rrow[i]];
            u64 scp = pk2(sc, sc);
            o2[i][0] = fmul2(o2[i][0], scp);
            o2[i][1] = fmul2(o2[i][1], scp);
        }
#pragma unroll 4
        for (int m = 0; m < 128; m++) {
            ulonglong2 vp = *(const ulonglong2*)(Vsm + m * VSP + txo * 4);
            float p0 = Ps[rrow[0] * PSP + m];
            float p1 = Ps[rrow[1] * PSP + m];
            float p2 = Ps[rrow[2] * PSP + m];
            float p3 = Ps[rrow[3] * PSP + m];
            u64 pd0 = pk2(p0, p0), pd1 = pk2(p1, p1);
            u64 pd2 = pk2(p2, p2), pd3 = pk2(p3, p3);
            o2[0][0] = ffma2(pd0, vp.x, o2[0][0]); o2[0][1] = ffma2(pd0, vp.y, o2[0][1]);
            o2[1][0] = ffma2(pd1, vp.x, o2[1][0]); o2[1][1] = ffma2(pd1, vp.y, o2[1][1]);
            o2[2][0] = ffma2(pd2, vp.x, o2[2][0]); o2[2][1] = ffma2(pd2, vp.y, o2[2][1]);
            o2[3][0] = ffma2(pd3, vp.x, o2[3][0]); o2[3][1] = ffma2(pd3, vp.y, o2[3][1]);
        }
        __syncthreads();
    }

    // ---- finalize: normalize, stage to smem [d][n], coalesced store ----
    if (tx == 0) {
#pragma unroll
        for (int i = 0; i < 8; i++) rs_s[ty * 8 + i] = rs[i];
    }
    __syncthreads();
#pragma unroll
    for (int i = 0; i < 4; i++) {
        float inv = 1.0f / rs_s[rrow[i]];
        float2 f0 = up2(o2[i][0]);
        float2 f1 = up2(o2[i][1]);
        Ps[(txo * 4 + 0) * PSP + rrow[i]] = f0.x * inv;
        Ps[(txo * 4 + 1) * PSP + rrow[i]] = f0.y * inv;
        Ps[(txo * 4 + 2) * PSP + rrow[i]] = f1.x * inv;
        Ps[(txo * 4 + 3) * PSP + rrow[i]] = f1.y * inv;
    }
    __syncthreads();
    const size_t obase = (((size_t)(b * 256 + h * 32)) << 12) + a * 1024 + n0;
#pragma unroll
    for (int it = 0; it < 4; it++) {
        int e4 = tid + it * 256;
        int d = e4 >> 5, c4 = e4 & 31;
        *(float4*)(g_o + obase + (size_t)d * 4096 + c4 * 4) =
            *(float4*)(Ps + d * PSP + c4 * 4);
    }
}

// =====================================================================
// Kernel 4: proj 1x1 conv GEMM with folded BN, input = g_o + g_pp.
// Tiles 64oc x 128pix, f32x2 pairs, grid (64,4)=256 blocks.
// =====================================================================
__global__ void __launch_bounds__(256, 2) k_proj(
    const float* __restrict__ w_proj,
    const float* __restrict__ pr_g, const float* __restrict__ pr_b,
    const float* __restrict__ pr_m, const float* __restrict__ pr_v,
    float* __restrict__ out)
{
    __shared__ float As2[16 * 128];
    __shared__ float Bs [16 * 128];

    const int tid = threadIdx.x;
    const int p0  = blockIdx.x * 128;
    const int b   = p0 >> 12;
    const int n0  = p0 & (NPIX - 1);
    const int oc0 = blockIdx.y * 64;
    const int ty  = tid >> 4, tx = tid & 15;

    u64 acc[4][4];
#pragma unroll
    for (int i = 0; i < 4; i++)
#pragma unroll
        for (int j = 0; j < 4; j++) acc[i][j] = 0ULL;

    const int row_l = tid >> 2;
    const int cpart = (tid & 3) * 4;
    const float* wrow = w_proj + (size_t)(oc0 + row_l) * 256;
    u64* As2u = (u64*)As2;

    for (int c0 = 0; c0 < 256; c0 += 16) {
        float4 w = *(const float4*)(wrow + c0 + cpart);
        As2u[(cpart + 0) * 64 + row_l] = pk2(w.x, w.x);
        As2u[(cpart + 1) * 64 + row_l] = pk2(w.y, w.y);
        As2u[(cpart + 2) * 64 + row_l] = pk2(w.z, w.z);
        As2u[(cpart + 3) * 64 + row_l] = pk2(w.w, w.w);
#pragma unroll
        for (int it = 0; it < 2; it++) {
            int e4 = tid + it * 256;
            int c_l = e4 >> 5, p4 = e4 & 31;
            size_t idx = (((size_t)(b * 256 + c0 + c_l)) << 12) + n0 + p4 * 4;
            float4 ov = *(const float4*)(g_o + idx);
            float4 pv = *(const float4*)(g_pp + idx);
            *(float4*)(Bs + c_l * 128 + p4 * 4) =
                make_float4(ov.x + pv.x, ov.y + pv.y, ov.z + pv.z, ov.w + pv.w);
        }
        __syncthreads();
#pragma unroll
        for (int kk = 0; kk < 16; kk++) {
            const u64* Au = (const u64*)As2 + kk * 64 + ty * 4;
            ulonglong2 a01 = *(const ulonglong2*)(Au);
            ulonglong2 a23 = *(const ulonglong2*)(Au + 2);
            const u64* Bu = (const u64*)Bs + kk * 64 + tx * 4;
            ulonglong2 b01 = *(const ulonglong2*)(Bu);
            ulonglong2 b23 = *(const ulonglong2*)(Bu + 2);
            u64 av[4] = {a01.x, a01.y, a23.x, a23.y};
            u64 bv[4] = {b01.x, b01.y, b23.x, b23.y};
#pragma unroll
            for (int i = 0; i < 4; i++)
#pragma unroll
                for (int j = 0; j < 4; j++) acc[i][j] = ffma2(av[i], bv[j], acc[i][j]);
        }
        __syncthreads();
    }

#pragma unroll
    for (int i = 0; i < 4; i++) {
        int oc = oc0 + ty * 4 + i;
        float sc = __ldg(pr_g + oc) * rsqrtf(__ldg(pr_v + oc) + EPS);
        float t  = __ldg(pr_b + oc) - __ldg(pr_m + oc) * sc;
        float* dst = out + (((size_t)(b * 256 + oc)) << 12) + n0;
        float2 f0 = up2(acc[i][0]), f1 = up2(acc[i][1]);
        float2 f2 = up2(acc[i][2]), f3 = up2(acc[i][3]);
        *(float4*)(dst + tx * 8)     = make_float4(f0.x * sc + t, f0.y * sc + t,
                                                   f1.x * sc + t, f1.y * sc + t);
        *(float4*)(dst + tx * 8 + 4) = make_float4(f2.x * sc + t, f2.y * sc + t,
                                                   f3.x * sc + t, f3.y * sc + t);
    }
}

// =====================================================================
// launch
// =====================================================================
extern "C" void kernel_launch(void* const* d_in, const int* in_sizes, int n_in,
                              void* d_out, int out_size)
{
    const float *x, *w_qk, *w_v, *w_pe, *w_proj;
    const float *qk_g, *qk_b, *qk_m, *qk_v;
    const float *v_g, *v_b, *v_m, *v_v;
    const float *pe_g, *pe_b, *pe_m, *pe_v;
    const float *pr_g, *pr_b, *pr_m, *pr_v;

    #define F(i) ((const float*)d_in[(i)])
    if (in_sizes[2] == 512) {
        x = F(0);  w_qk = F(1);
        qk_g = F(2);  qk_b = F(3);  qk_m = F(4);  qk_v = F(5);
        w_v = F(6);
        v_g = F(7);   v_b = F(8);   v_m = F(9);   v_v = F(10);
        w_pe = F(11);
        pe_g = F(12); pe_b = F(13); pe_m = F(14); pe_v = F(15);
        w_proj = F(16);
        pr_g = F(17); pr_b = F(18); pr_m = F(19); pr_v = F(20);
    } else {
        x = F(0); w_qk = F(1); w_v = F(2); w_pe = F(3); w_proj = F(4);
        qk_g = F(5);  qk_b = F(6);  qk_m = F(7);  qk_v = F(8);
        v_g = F(9);   v_b = F(10);  v_m = F(11);  v_v = F(12);
        pe_g = F(13); pe_b = F(14); pe_m = F(15); pe_v = F(16);
        pr_g = F(17); pr_b = F(18); pr_m = F(19); pr_v = F(20);
    }
    #undef F

    cudaFuncSetAttribute(k_attn, cudaFuncAttributeMaxDynamicSharedMemorySize,
                         ATT_SMEM_BYTES);

    k_qkv<<<dim3(64, 12), 256>>>(x, w_qk, w_v,
                                 qk_g, qk_b, qk_m, qk_v,
                                 v_g, v_b, v_m, v_v);
    k_pe<<<(B_ * C_ * NPIX) / 256, 256>>>(w_pe, pe_g, pe_b, pe_m, pe_v);
    k_attn<<<dim3(8, 64), 256, ATT_SMEM_BYTES>>>();
    k_proj<<<dim3(64, 4), 256>>>(w_proj, pr_g, pr_b, pr_m, pr_v, (float*)d_out);
}